// round 7
// baseline (speedup 1.0000x reference)
#include <cuda_runtime.h>
#include <cstdint>

// Causal SDPA, tf32 tensor-core flash attention (mma.sync.m16n8k8.tf32).
// B=4, H=12, S=2048, D=64. Inputs (metadata order): keys, queries, values.
//
// CTA = 128 threads (4 warps), Q tile 64 (16 rows/warp), KV tile 64.
// Q fragments hoisted to registers (loop-invariant) -> no Q smem buffer;
// smem = K + V tiles only (34.8 KB) -> 6 CTAs/SM. P stays in registers via
// the key-permutation PV trick. Goal: saturate the smem crossbar.

#define SEQ 2048
#define DH 64
#define QT 64
#define KT 64
#define QSTR 68
#define KSTR 68
#define VSTR 68

__device__ __forceinline__ float tf32r(float x) {
    asm("cvt.rna.tf32.f32 %0, %0;" : "+f"(x));
    return x;
}
__device__ __forceinline__ uint32_t tf32u(float x) {
    asm("cvt.rna.tf32.f32 %0, %0;" : "+f"(x));
    return __float_as_uint(x);
}

__device__ __forceinline__ void mma_tf32(float c[4],
                                         uint32_t a0, uint32_t a1, uint32_t a2, uint32_t a3,
                                         uint32_t b0, uint32_t b1) {
    asm volatile("mma.sync.aligned.m16n8k8.row.col.f32.tf32.tf32.f32 "
                 "{%0,%1,%2,%3}, {%4,%5,%6,%7}, {%8,%9}, {%0,%1,%2,%3};"
                 : "+f"(c[0]), "+f"(c[1]), "+f"(c[2]), "+f"(c[3])
                 : "r"(a0), "r"(a1), "r"(a2), "r"(a3), "r"(b0), "r"(b1));
}

__global__ __launch_bounds__(128, 6)
void fa_tf32_kernel(const float* __restrict__ Kg_, const float* __restrict__ Qg_,
                    const float* __restrict__ Vg_, float* __restrict__ Og_)
{
    extern __shared__ float sm[];
    float* Ks = sm;                    // 64 x 68
    float* Vs = Ks + KT * KSTR;        // 64 x 68

    const int qt   = gridDim.x - 1 - blockIdx.x;   // heavy tiles first
    const int bh   = blockIdx.y;
    const int tid  = threadIdx.x;
    const int w    = tid >> 5;
    const int lane = tid & 31;
    const int lr   = lane >> 2;        // 0..7
    const int lc   = lane & 3;         // 0..3

    const size_t base = (size_t)bh * SEQ * DH;
    const float4* Qg = (const float4*)(Qg_ + base);
    const float4* Kg = (const float4*)(Kg_ + base);
    const float4* Vg = (const float4*)(Vg_ + base);

    const uint32_t* Ksu = (const uint32_t*)Ks;
    const uint32_t* Vsu = (const uint32_t*)Vs;

    const int rl = w * 16 + lr;        // warp-local Q row (lo half)

    // ---- stage Q tile through Ks, pull fragments into registers ----
    uint32_t aq[8][4];
    {
        #pragma unroll
        for (int i = 0; i < 8; i++) {
            int idx = tid + i * 128;           // 0..1023
            int row = idx >> 4, c4 = idx & 15;
            float4 q = Qg[(qt * QT + row) * 16 + c4];
            q.x = tf32r(q.x * 0.125f); q.y = tf32r(q.y * 0.125f);
            q.z = tf32r(q.z * 0.125f); q.w = tf32r(q.w * 0.125f);
            *(float4*)&Ks[row * KSTR + c4 * 4] = q;
        }
        __syncthreads();
        #pragma unroll
        for (int k = 0; k < 8; k++) {
            aq[k][0] = Ksu[ rl      * KSTR + k * 8 + lc];
            aq[k][1] = Ksu[(rl + 8) * KSTR + k * 8 + lc];
            aq[k][2] = Ksu[ rl      * KSTR + k * 8 + lc + 4];
            aq[k][3] = Ksu[(rl + 8) * KSTR + k * 8 + lc + 4];
        }
        // NOTE: next __syncthreads (top of kt loop) orders these reads
        // before the first K tile overwrites Ks.
    }

    float o[8][4];
    float m0 = -1e30f, m1 = -1e30f, l0 = 0.f, l1 = 0.f;
    #pragma unroll
    for (int n = 0; n < 8; n++)
        #pragma unroll
        for (int j = 0; j < 4; j++) o[n][j] = 0.f;

    const int ktmax = qt + 1;

    for (int kt = 0; kt < ktmax; kt++) {
        __syncthreads();                   // prior reads of Ks/Vs done
        // ---- load K, V tiles (tf32 rna) ----
        #pragma unroll
        for (int i = 0; i < 8; i++) {
            int idx = tid + i * 128;
            int row = idx >> 4, c4 = idx & 15;
            float4 k = Kg[(kt * KT + row) * 16 + c4];
            k.x = tf32r(k.x); k.y = tf32r(k.y); k.z = tf32r(k.z); k.w = tf32r(k.w);
            *(float4*)&Ks[row * KSTR + c4 * 4] = k;
            float4 v = Vg[(kt * KT + row) * 16 + c4];
            v.x = tf32r(v.x); v.y = tf32r(v.y); v.z = tf32r(v.z); v.w = tf32r(v.w);
            *(float4*)&Vs[row * VSTR + c4 * 4] = v;
        }
        __syncthreads();

        // ---- QK: S[16x64] ----
        float s[8][4];
        #pragma unroll
        for (int n = 0; n < 8; n++)
            #pragma unroll
            for (int j = 0; j < 4; j++) s[n][j] = 0.f;

        #pragma unroll
        for (int k = 0; k < 8; k++) {
            #pragma unroll
            for (int n = 0; n < 8; n++) {
                uint32_t b0 = Ksu[(n * 8 + lr) * KSTR + k * 8 + lc];
                uint32_t b1 = Ksu[(n * 8 + lr) * KSTR + k * 8 + lc + 4];
                mma_tf32(s[n], aq[k][0], aq[k][1], aq[k][2], aq[k][3], b0, b1);
            }
        }

        // ---- causal mask (diagonal tile only) ----
        if (kt == qt) {
            int qlo = w * 16 + lr;
            int qhi = qlo + 8;
            #pragma unroll
            for (int n = 0; n < 8; n++) {
                int key = n * 8 + 2 * lc;
                if (key     > qlo) s[n][0] = -1e30f;
                if (key + 1 > qlo) s[n][1] = -1e30f;
                if (key     > qhi) s[n][2] = -1e30f;
                if (key + 1 > qhi) s[n][3] = -1e30f;
            }
        }

        // ---- online softmax ----
        float rmx0 = -1e30f, rmx1 = -1e30f;
        #pragma unroll
        for (int n = 0; n < 8; n++) {
            rmx0 = fmaxf(rmx0, fmaxf(s[n][0], s[n][1]));
            rmx1 = fmaxf(rmx1, fmaxf(s[n][2], s[n][3]));
        }
        rmx0 = fmaxf(rmx0, __shfl_xor_sync(0xffffffffu, rmx0, 1));
        rmx0 = fmaxf(rmx0, __shfl_xor_sync(0xffffffffu, rmx0, 2));
        rmx1 = fmaxf(rmx1, __shfl_xor_sync(0xffffffffu, rmx1, 1));
        rmx1 = fmaxf(rmx1, __shfl_xor_sync(0xffffffffu, rmx1, 2));

        float mn0 = fmaxf(m0, rmx0);
        float mn1 = fmaxf(m1, rmx1);
        float corr0 = __expf(m0 - mn0);
        float corr1 = __expf(m1 - mn1);
        m0 = mn0; m1 = mn1;

        float ps0 = 0.f, ps1 = 0.f;
        #pragma unroll
        for (int n = 0; n < 8; n++) {
            s[n][0] = __expf(s[n][0] - mn0);
            s[n][1] = __expf(s[n][1] - mn0);
            s[n][2] = __expf(s[n][2] - mn1);
            s[n][3] = __expf(s[n][3] - mn1);
            ps0 += s[n][0] + s[n][1];
            ps1 += s[n][2] + s[n][3];
        }
        ps0 += __shfl_xor_sync(0xffffffffu, ps0, 1);
        ps0 += __shfl_xor_sync(0xffffffffu, ps0, 2);
        ps1 += __shfl_xor_sync(0xffffffffu, ps1, 1);
        ps1 += __shfl_xor_sync(0xffffffffu, ps1, 2);
        l0 = l0 * corr0 + ps0;
        l1 = l1 * corr1 + ps1;

        #pragma unroll
        for (int n = 0; n < 8; n++) {
            o[n][0] *= corr0; o[n][1] *= corr0;
            o[n][2] *= corr1; o[n][3] *= corr1;
        }

        // ---- PV: O += P * V (P in regs via key permutation) ----
        #pragma unroll
        for (int k = 0; k < 8; k++) {
            uint32_t a0 = tf32u(s[k][0]);
            uint32_t a1 = tf32u(s[k][2]);
            uint32_t a2 = tf32u(s[k][1]);
            uint32_t a3 = tf32u(s[k][3]);
            #pragma unroll
            for (int n = 0; n < 8; n++) {
                uint32_t b0 = Vsu[(k * 8 + 2 * lc)     * VSTR + n * 8 + lr];
                uint32_t b1 = Vsu[(k * 8 + 2 * lc + 1) * VSTR + n * 8 + lr];
                mma_tf32(o[n], a0, a1, a2, a3, b0, b1);
            }
        }
    }

    // ---- epilogue: normalize + store ----
    float2* Og = (float2*)(Og_ + base);
    {
        float inv0 = 1.0f / l0;
        float inv1 = 1.0f / l1;
        int grow = qt * QT + w * 16 + lr;
        #pragma unroll
        for (int n = 0; n < 8; n++) {
            Og[ grow      * 32 + n * 4 + lc] = make_float2(o[n][0] * inv0, o[n][1] * inv0);
            Og[(grow + 8) * 32 + n * 4 + lc] = make_float2(o[n][2] * inv1, o[n][3] * inv1);
        }
    }
}

extern "C" void kernel_launch(void* const* d_in, const int* in_sizes, int n_in,
                              void* d_out, int out_size) {
    const float* K = (const float*)d_in[0];
    const float* Q = (const float*)d_in[1];
    const float* V = (const float*)d_in[2];
    float* O = (float*)d_out;

    size_t smem = (size_t)(KT * KSTR + KT * VSTR) * sizeof(float);  // 34816 B
    cudaFuncSetAttribute(fa_tf32_kernel,
                         cudaFuncAttributeMaxDynamicSharedMemorySize, (int)smem);

    dim3 grid(SEQ / QT, 48);
    fa_tf32_kernel<<<grid, 128, (int)smem>>>(K, Q, V, O);
}

// round 8
// speedup vs baseline: 1.4680x; 1.4680x over previous
#include <cuda_runtime.h>
#include <cstdint>

// Causal SDPA, tf32 tensor-core flash attention (mma.sync.m16n8k8.tf32).
// B=4, H=12, S=2048, D=64. Inputs (metadata order): keys, queries, values.
//
// CTA = 128 threads (4 warps), Q tile 128 (32 rows/warp = 2 x m16), KV tile 64.
// K and V fragments are loaded ONCE per (k,n) and shared across both m-blocks
// (2 MMAs per fragment load) -> ~1.6x less smem-crossbar traffic per MMA.
// P stays in registers via the key-permutation PV trick. Q in smem.

#define SEQ 2048
#define DH 64
#define QT 128
#define KT 64
#define QSTR 68
#define KSTR 68
#define VSTR 68

__device__ __forceinline__ float tf32r(float x) {
    asm("cvt.rna.tf32.f32 %0, %0;" : "+f"(x));
    return x;
}
__device__ __forceinline__ uint32_t tf32u(float x) {
    asm("cvt.rna.tf32.f32 %0, %0;" : "+f"(x));
    return __float_as_uint(x);
}

__device__ __forceinline__ void mma_tf32(float c[4],
                                         uint32_t a0, uint32_t a1, uint32_t a2, uint32_t a3,
                                         uint32_t b0, uint32_t b1) {
    asm volatile("mma.sync.aligned.m16n8k8.row.col.f32.tf32.tf32.f32 "
                 "{%0,%1,%2,%3}, {%4,%5,%6,%7}, {%8,%9}, {%0,%1,%2,%3};"
                 : "+f"(c[0]), "+f"(c[1]), "+f"(c[2]), "+f"(c[3])
                 : "r"(a0), "r"(a1), "r"(a2), "r"(a3), "r"(b0), "r"(b1));
}

__global__ __launch_bounds__(128, 3)
void fa_tf32_kernel(const float* __restrict__ Kg_, const float* __restrict__ Qg_,
                    const float* __restrict__ Vg_, float* __restrict__ Og_)
{
    extern __shared__ float sm[];
    float* Qs = sm;                    // 128 x 68
    float* Ks = Qs + QT * QSTR;        // 64 x 68
    float* Vs = Ks + KT * KSTR;        // 64 x 68

    const int qt   = gridDim.x - 1 - blockIdx.x;   // heavy tiles first
    const int bh   = blockIdx.y;
    const int tid  = threadIdx.x;
    const int w    = tid >> 5;
    const int lane = tid & 31;
    const int lr   = lane >> 2;        // 0..7
    const int lc   = lane & 3;         // 0..3

    const size_t base = (size_t)bh * SEQ * DH;
    const float4* Qg = (const float4*)(Qg_ + base);
    const float4* Kg = (const float4*)(Kg_ + base);
    const float4* Vg = (const float4*)(Vg_ + base);

    // ---- load Q tile (pre-scaled by 1/8, tf32 rna) ----
    #pragma unroll
    for (int i = 0; i < 16; i++) {
        int idx = tid + i * 128;
        int row = idx >> 4, c4 = idx & 15;
        float4 q = Qg[(qt * QT + row) * 16 + c4];
        q.x = tf32r(q.x * 0.125f); q.y = tf32r(q.y * 0.125f);
        q.z = tf32r(q.z * 0.125f); q.w = tf32r(q.w * 0.125f);
        *(float4*)&Qs[row * QSTR + c4 * 4] = q;
    }

    float o[2][8][4];
    float m[2][2], l[2][2];
    #pragma unroll
    for (int mb = 0; mb < 2; mb++) {
        m[mb][0] = -1e30f; m[mb][1] = -1e30f;
        l[mb][0] = 0.f;    l[mb][1] = 0.f;
        #pragma unroll
        for (int n = 0; n < 8; n++)
            #pragma unroll
            for (int j = 0; j < 4; j++) o[mb][n][j] = 0.f;
    }

    const int ktmax    = 2 * qt + 2;
    const int wrow_min = qt * QT + w * 32;
    const int wrow_max = wrow_min + 31;

    const uint32_t* Qsu = (const uint32_t*)Qs;
    const uint32_t* Ksu = (const uint32_t*)Ks;
    const uint32_t* Vsu = (const uint32_t*)Vs;

    for (int kt = 0; kt < ktmax; kt++) {
        __syncthreads();
        // ---- load K, V tiles (tf32 rna) ----
        #pragma unroll
        for (int i = 0; i < 8; i++) {
            int idx = tid + i * 128;
            int row = idx >> 4, c4 = idx & 15;
            float4 k = Kg[(kt * KT + row) * 16 + c4];
            k.x = tf32r(k.x); k.y = tf32r(k.y); k.z = tf32r(k.z); k.w = tf32r(k.w);
            *(float4*)&Ks[row * KSTR + c4 * 4] = k;
            float4 v = Vg[(kt * KT + row) * 16 + c4];
            v.x = tf32r(v.x); v.y = tf32r(v.y); v.z = tf32r(v.z); v.w = tf32r(v.w);
            *(float4*)&Vs[row * VSTR + c4 * 4] = v;
        }
        __syncthreads();

        if (kt * KT <= wrow_max) {
            const bool diag = (kt * KT + KT - 1 > wrow_min);

            // ---- QK: S[2][16x64], K fragments shared across m-blocks ----
            float s[2][8][4];
            #pragma unroll
            for (int mb = 0; mb < 2; mb++)
                #pragma unroll
                for (int n = 0; n < 8; n++)
                    #pragma unroll
                    for (int j = 0; j < 4; j++) s[mb][n][j] = 0.f;

            #pragma unroll
            for (int k = 0; k < 8; k++) {
                const int r0 = w * 32 + lr;
                uint32_t a00 = Qsu[ r0       * QSTR + k * 8 + lc];
                uint32_t a01 = Qsu[(r0 +  8) * QSTR + k * 8 + lc];
                uint32_t a02 = Qsu[ r0       * QSTR + k * 8 + lc + 4];
                uint32_t a03 = Qsu[(r0 +  8) * QSTR + k * 8 + lc + 4];
                uint32_t a10 = Qsu[(r0 + 16) * QSTR + k * 8 + lc];
                uint32_t a11 = Qsu[(r0 + 24) * QSTR + k * 8 + lc];
                uint32_t a12 = Qsu[(r0 + 16) * QSTR + k * 8 + lc + 4];
                uint32_t a13 = Qsu[(r0 + 24) * QSTR + k * 8 + lc + 4];
                #pragma unroll
                for (int n = 0; n < 8; n++) {
                    uint32_t b0 = Ksu[(n * 8 + lr) * KSTR + k * 8 + lc];
                    uint32_t b1 = Ksu[(n * 8 + lr) * KSTR + k * 8 + lc + 4];
                    mma_tf32(s[0][n], a00, a01, a02, a03, b0, b1);
                    mma_tf32(s[1][n], a10, a11, a12, a13, b0, b1);
                }
            }

            // ---- mask + online softmax per m-block ----
            #pragma unroll
            for (int mb = 0; mb < 2; mb++) {
                if (diag) {
                    int qlo = qt * QT + w * 32 + mb * 16 + lr;
                    int qhi = qlo + 8;
                    #pragma unroll
                    for (int n = 0; n < 8; n++) {
                        int key = kt * KT + n * 8 + 2 * lc;
                        if (key     > qlo) s[mb][n][0] = -1e30f;
                        if (key + 1 > qlo) s[mb][n][1] = -1e30f;
                        if (key     > qhi) s[mb][n][2] = -1e30f;
                        if (key + 1 > qhi) s[mb][n][3] = -1e30f;
                    }
                }

                float rmx0 = -1e30f, rmx1 = -1e30f;
                #pragma unroll
                for (int n = 0; n < 8; n++) {
                    rmx0 = fmaxf(rmx0, fmaxf(s[mb][n][0], s[mb][n][1]));
                    rmx1 = fmaxf(rmx1, fmaxf(s[mb][n][2], s[mb][n][3]));
                }
                rmx0 = fmaxf(rmx0, __shfl_xor_sync(0xffffffffu, rmx0, 1));
                rmx0 = fmaxf(rmx0, __shfl_xor_sync(0xffffffffu, rmx0, 2));
                rmx1 = fmaxf(rmx1, __shfl_xor_sync(0xffffffffu, rmx1, 1));
                rmx1 = fmaxf(rmx1, __shfl_xor_sync(0xffffffffu, rmx1, 2));

                float mn0 = fmaxf(m[mb][0], rmx0);
                float mn1 = fmaxf(m[mb][1], rmx1);
                float corr0 = __expf(m[mb][0] - mn0);
                float corr1 = __expf(m[mb][1] - mn1);
                m[mb][0] = mn0; m[mb][1] = mn1;

                float ps0 = 0.f, ps1 = 0.f;
                #pragma unroll
                for (int n = 0; n < 8; n++) {
                    s[mb][n][0] = __expf(s[mb][n][0] - mn0);
                    s[mb][n][1] = __expf(s[mb][n][1] - mn0);
                    s[mb][n][2] = __expf(s[mb][n][2] - mn1);
                    s[mb][n][3] = __expf(s[mb][n][3] - mn1);
                    ps0 += s[mb][n][0] + s[mb][n][1];
                    ps1 += s[mb][n][2] + s[mb][n][3];
                }
                ps0 += __shfl_xor_sync(0xffffffffu, ps0, 1);
                ps0 += __shfl_xor_sync(0xffffffffu, ps0, 2);
                ps1 += __shfl_xor_sync(0xffffffffu, ps1, 1);
                ps1 += __shfl_xor_sync(0xffffffffu, ps1, 2);
                l[mb][0] = l[mb][0] * corr0 + ps0;
                l[mb][1] = l[mb][1] * corr1 + ps1;

                #pragma unroll
                for (int n = 0; n < 8; n++) {
                    o[mb][n][0] *= corr0; o[mb][n][1] *= corr0;
                    o[mb][n][2] *= corr1; o[mb][n][3] *= corr1;
                }
            }

            // ---- PV: V fragments shared across m-blocks (P in regs, permuted) ----
            #pragma unroll
            for (int k = 0; k < 8; k++) {
                uint32_t ua00 = tf32u(s[0][k][0]);
                uint32_t ua01 = tf32u(s[0][k][2]);
                uint32_t ua02 = tf32u(s[0][k][1]);
                uint32_t ua03 = tf32u(s[0][k][3]);
                uint32_t ua10 = tf32u(s[1][k][0]);
                uint32_t ua11 = tf32u(s[1][k][2]);
                uint32_t ua12 = tf32u(s[1][k][1]);
                uint32_t ua13 = tf32u(s[1][k][3]);
                #pragma unroll
                for (int n = 0; n < 8; n++) {
                    uint32_t b0 = Vsu[(k * 8 + 2 * lc)     * VSTR + n * 8 + lr];
                    uint32_t b1 = Vsu[(k * 8 + 2 * lc + 1) * VSTR + n * 8 + lr];
                    mma_tf32(o[0][n], ua00, ua01, ua02, ua03, b0, b1);
                    mma_tf32(o[1][n], ua10, ua11, ua12, ua13, b0, b1);
                }
            }
        }
    }

    // ---- epilogue: normalize + store ----
    float2* Og = (float2*)(Og_ + base);
    #pragma unroll
    for (int mb = 0; mb < 2; mb++) {
        float inv0 = 1.0f / l[mb][0];
        float inv1 = 1.0f / l[mb][1];
        int grow = qt * QT + w * 32 + mb * 16 + lr;
        #pragma unroll
        for (int n = 0; n < 8; n++) {
            Og[ grow      * 32 + n * 4 + lc] = make_float2(o[mb][n][0] * inv0, o[mb][n][1] * inv0);
            Og[(grow + 8) * 32 + n * 4 + lc] = make_float2(o[mb][n][2] * inv1, o[mb][n][3] * inv1);
        }
    }
}

extern "C" void kernel_launch(void* const* d_in, const int* in_sizes, int n_in,
                              void* d_out, int out_size) {
    const float* K = (const float*)d_in[0];
    const float* Q = (const float*)d_in[1];
    const float* V = (const float*)d_in[2];
    float* O = (float*)d_out;

    size_t smem = (size_t)(QT * QSTR + KT * KSTR + KT * VSTR) * sizeof(float);  // 69632 B
    cudaFuncSetAttribute(fa_tf32_kernel,
                         cudaFuncAttributeMaxDynamicSharedMemorySize, (int)smem);

    dim3 grid(SEQ / QT, 48);
    fa_tf32_kernel<<<grid, 128, (int)smem>>>(K, Q, V, O);
}

// round 9
// speedup vs baseline: 1.6031x; 1.0921x over previous
#include <cuda_runtime.h>
#include <cstdint>

// Causal SDPA, tf32 tensor-core flash attention (mma.sync.m16n8k8.tf32).
// B=4, H=12, S=2048, D=64. Inputs (metadata order): keys, queries, values.
//
// CTA = 128 threads (4 warps), Q tile 64 (16 rows/warp), KV tile 64.
// - Q fragments hoisted to registers (staged once through smem).
// - K/V double-buffered via cp.async, prefetch issued a full tile ahead.
// - V converted to tf32(rna) by an in-smem pass; K fed raw (HW rz truncation).
// - P stays in registers via the key-permutation PV trick.

#define SEQ 2048
#define DH 64
#define QT 64
#define KT 64
#define KSTR 68
#define VSTR 68
#define STAGE (KT * KSTR)          // floats per K (or V) stage

__device__ __forceinline__ float tf32r(float x) {
    asm("cvt.rna.tf32.f32 %0, %0;" : "+f"(x));
    return x;
}
__device__ __forceinline__ uint32_t tf32u(float x) {
    asm("cvt.rna.tf32.f32 %0, %0;" : "+f"(x));
    return __float_as_uint(x);
}

__device__ __forceinline__ void mma_tf32(float c[4],
                                         uint32_t a0, uint32_t a1, uint32_t a2, uint32_t a3,
                                         uint32_t b0, uint32_t b1) {
    asm volatile("mma.sync.aligned.m16n8k8.row.col.f32.tf32.tf32.f32 "
                 "{%0,%1,%2,%3}, {%4,%5,%6,%7}, {%8,%9}, {%0,%1,%2,%3};"
                 : "+f"(c[0]), "+f"(c[1]), "+f"(c[2]), "+f"(c[3])
                 : "r"(a0), "r"(a1), "r"(a2), "r"(a3), "r"(b0), "r"(b1));
}

__device__ __forceinline__ void cp16(uint32_t saddr, const void* gaddr) {
    asm volatile("cp.async.cg.shared.global [%0], [%1], 16;" :: "r"(saddr), "l"(gaddr));
}
__device__ __forceinline__ void cp_commit() {
    asm volatile("cp.async.commit_group;");
}
__device__ __forceinline__ void cp_wait0() {
    asm volatile("cp.async.wait_group 0;");
}

__global__ __launch_bounds__(128, 3)
void fa_tf32_kernel(const float* __restrict__ Kg_, const float* __restrict__ Qg_,
                    const float* __restrict__ Vg_, float* __restrict__ Og_)
{
    extern __shared__ float sm[];
    float* Kb = sm;                    // 2 stages x (64 x 68)
    float* Vb = Kb + 2 * STAGE;        // 2 stages x (64 x 68)

    const int qt   = gridDim.x - 1 - blockIdx.x;   // heavy tiles first
    const int bh   = blockIdx.y;
    const int tid  = threadIdx.x;
    const int w    = tid >> 5;
    const int lane = tid & 31;
    const int lr   = lane >> 2;        // 0..7
    const int lc   = lane & 3;         // 0..3

    const size_t base = (size_t)bh * SEQ * DH;
    const float4* Qg = (const float4*)(Qg_ + base);
    const float4* Kg = (const float4*)(Kg_ + base);
    const float4* Vg = (const float4*)(Vg_ + base);

    const int crow = tid >> 4;         // cp slice: base row 0..7
    const int cc4  = tid & 15;         // cp slice: float4 col

    const uint32_t KbU = (uint32_t)__cvta_generic_to_shared(Kb);
    const uint32_t VbU = (uint32_t)__cvta_generic_to_shared(Vb);

    const int rl = w * 16 + lr;        // warp-local Q row (lo half)

    // ---- stage Q tile through Kb[0], hoist fragments to registers ----
    uint32_t aq[8][4];
    {
        #pragma unroll
        for (int i = 0; i < 8; i++) {
            int idx = tid + i * 128;              // 0..1023
            int row = idx >> 4, c4 = idx & 15;
            float4 q = Qg[(qt * QT + row) * 16 + c4];
            q.x = tf32r(q.x * 0.125f); q.y = tf32r(q.y * 0.125f);
            q.z = tf32r(q.z * 0.125f); q.w = tf32r(q.w * 0.125f);
            *(float4*)&Kb[row * KSTR + c4 * 4] = q;
        }
        __syncthreads();
        const uint32_t* Q0 = (const uint32_t*)Kb;
        #pragma unroll
        for (int k = 0; k < 8; k++) {
            aq[k][0] = Q0[ rl      * KSTR + k * 8 + lc];
            aq[k][1] = Q0[(rl + 8) * KSTR + k * 8 + lc];
            aq[k][2] = Q0[ rl      * KSTR + k * 8 + lc + 4];
            aq[k][3] = Q0[(rl + 8) * KSTR + k * 8 + lc + 4];
        }
        __syncthreads();   // all Q reads done before cp overwrites Kb[0]
    }

    // ---- prologue: prefetch KV tile 0 into stage 0 ----
    #pragma unroll
    for (int i = 0; i < 8; i++) {
        int row = crow + i * 8;
        uint32_t soff = (uint32_t)(row * KSTR + cc4 * 4) * 4u;
        cp16(KbU + soff, Kg + (size_t)row * 16 + cc4);
        cp16(VbU + soff, Vg + (size_t)row * 16 + cc4);
    }
    cp_commit();

    float o[8][4];
    float m0 = -1e30f, m1 = -1e30f, l0 = 0.f, l1 = 0.f;
    #pragma unroll
    for (int n = 0; n < 8; n++)
        #pragma unroll
        for (int j = 0; j < 4; j++) o[n][j] = 0.f;

    const int ktmax = qt + 1;

    for (int kt = 0; kt < ktmax; kt++) {
        const int cur = kt & 1;

        cp_wait0();            // tile kt arrived (sole group in flight)
        __syncthreads();       // (B) visibility of all threads' copies;
                               //     also: all warps finished iter kt-1 reads

        // prefetch tile kt+1 into the other stage (its last readers are
        // guaranteed past barrier (B)), overlapping the whole compute phase
        if (kt + 1 < ktmax) {
            const int nxt = cur ^ 1;
            #pragma unroll
            for (int i = 0; i < 8; i++) {
                int row = crow + i * 8;
                uint32_t soff = (uint32_t)(nxt * STAGE + row * KSTR + cc4 * 4) * 4u;
                cp16(KbU + soff, Kg + (size_t)((kt + 1) * KT + row) * 16 + cc4);
                cp16(VbU + soff, Vg + (size_t)((kt + 1) * KT + row) * 16 + cc4);
            }
            cp_commit();
        }

        float* Vc = Vb + cur * STAGE;
        // ---- in-smem rna pass for V ----
        #pragma unroll
        for (int i = 0; i < 8; i++) {
            int idx = tid + i * 128;
            int row = idx >> 4, c4 = idx & 15;
            float4* vp = (float4*)&Vc[row * VSTR + c4 * 4];
            float4 v = *vp;
            v.x = tf32r(v.x); v.y = tf32r(v.y); v.z = tf32r(v.z); v.w = tf32r(v.w);
            *vp = v;
        }
        __syncthreads();       // (C) converted V visible

        const uint32_t* Ksu = (const uint32_t*)(Kb + cur * STAGE);
        const uint32_t* Vsu = (const uint32_t*)Vc;

        // ---- QK: S[16x64] (K raw f32 bits -> HW tf32 truncation) ----
        float s[8][4];
        #pragma unroll
        for (int n = 0; n < 8; n++)
            #pragma unroll
            for (int j = 0; j < 4; j++) s[n][j] = 0.f;

        #pragma unroll
        for (int k = 0; k < 8; k++) {
            #pragma unroll
            for (int n = 0; n < 8; n++) {
                uint32_t b0 = Ksu[(n * 8 + lr) * KSTR + k * 8 + lc];
                uint32_t b1 = Ksu[(n * 8 + lr) * KSTR + k * 8 + lc + 4];
                mma_tf32(s[n], aq[k][0], aq[k][1], aq[k][2], aq[k][3], b0, b1);
            }
        }

        // ---- causal mask (diagonal tile only) ----
        if (kt == qt) {
            int qlo = w * 16 + lr;
            int qhi = qlo + 8;
            #pragma unroll
            for (int n = 0; n < 8; n++) {
                int key = n * 8 + 2 * lc;
                if (key     > qlo) s[n][0] = -1e30f;
                if (key + 1 > qlo) s[n][1] = -1e30f;
                if (key     > qhi) s[n][2] = -1e30f;
                if (key + 1 > qhi) s[n][3] = -1e30f;
            }
        }

        // ---- online softmax ----
        float rmx0 = -1e30f, rmx1 = -1e30f;
        #pragma unroll
        for (int n = 0; n < 8; n++) {
            rmx0 = fmaxf(rmx0, fmaxf(s[n][0], s[n][1]));
            rmx1 = fmaxf(rmx1, fmaxf(s[n][2], s[n][3]));
        }
        rmx0 = fmaxf(rmx0, __shfl_xor_sync(0xffffffffu, rmx0, 1));
        rmx0 = fmaxf(rmx0, __shfl_xor_sync(0xffffffffu, rmx0, 2));
        rmx1 = fmaxf(rmx1, __shfl_xor_sync(0xffffffffu, rmx1, 1));
        rmx1 = fmaxf(rmx1, __shfl_xor_sync(0xffffffffu, rmx1, 2));

        float mn0 = fmaxf(m0, rmx0);
        float mn1 = fmaxf(m1, rmx1);
        float corr0 = __expf(m0 - mn0);
        float corr1 = __expf(m1 - mn1);
        m0 = mn0; m1 = mn1;

        float ps0 = 0.f, ps1 = 0.f;
        #pragma unroll
        for (int n = 0; n < 8; n++) {
            s[n][0] = __expf(s[n][0] - mn0);
            s[n][1] = __expf(s[n][1] - mn0);
            s[n][2] = __expf(s[n][2] - mn1);
            s[n][3] = __expf(s[n][3] - mn1);
            ps0 += s[n][0] + s[n][1];
            ps1 += s[n][2] + s[n][3];
        }
        ps0 += __shfl_xor_sync(0xffffffffu, ps0, 1);
        ps0 += __shfl_xor_sync(0xffffffffu, ps0, 2);
        ps1 += __shfl_xor_sync(0xffffffffu, ps1, 1);
        ps1 += __shfl_xor_sync(0xffffffffu, ps1, 2);
        l0 = l0 * corr0 + ps0;
        l1 = l1 * corr1 + ps1;

        #pragma unroll
        for (int n = 0; n < 8; n++) {
            o[n][0] *= corr0; o[n][1] *= corr0;
            o[n][2] *= corr1; o[n][3] *= corr1;
        }

        // ---- PV: O += P * V (P in regs via key permutation) ----
        #pragma unroll
        for (int k = 0; k < 8; k++) {
            uint32_t a0 = tf32u(s[k][0]);
            uint32_t a1 = tf32u(s[k][2]);
            uint32_t a2 = tf32u(s[k][1]);
            uint32_t a3 = tf32u(s[k][3]);
            #pragma unroll
            for (int n = 0; n < 8; n++) {
                uint32_t b0 = Vsu[(k * 8 + 2 * lc)     * VSTR + n * 8 + lr];
                uint32_t b1 = Vsu[(k * 8 + 2 * lc + 1) * VSTR + n * 8 + lr];
                mma_tf32(o[n], a0, a1, a2, a3, b0, b1);
            }
        }
    }

    // ---- epilogue: normalize + store ----
    float2* Og = (float2*)(Og_ + base);
    {
        float inv0 = 1.0f / l0;
        float inv1 = 1.0f / l1;
        int grow = qt * QT + w * 16 + lr;
        #pragma unroll
        for (int n = 0; n < 8; n++) {
            Og[ grow      * 32 + n * 4 + lc] = make_float2(o[n][0] * inv0, o[n][1] * inv0);
            Og[(grow + 8) * 32 + n * 4 + lc] = make_float2(o[n][2] * inv1, o[n][3] * inv1);
        }
    }
}

extern "C" void kernel_launch(void* const* d_in, const int* in_sizes, int n_in,
                              void* d_out, int out_size) {
    const float* K = (const float*)d_in[0];
    const float* Q = (const float*)d_in[1];
    const float* V = (const float*)d_in[2];
    float* O = (float*)d_out;

    size_t smem = (size_t)(4 * STAGE) * sizeof(float);   // 69632 B -> 3 CTAs/SM
    cudaFuncSetAttribute(fa_tf32_kernel,
                         cudaFuncAttributeMaxDynamicSharedMemorySize, (int)smem);

    dim3 grid(SEQ / QT, 48);
    fa_tf32_kernel<<<grid, 128, (int)smem>>>(K, Q, V, O);
}